// round 8
// baseline (speedup 1.0000x reference)
#include <cuda_runtime.h>

#define BB 64
#define HH 56
#define WW 56
#define CC 256
#define CO 64
#define NROUTES 4
#define CHUNKS 14
#define X_ELEMS (BB*HH*WW*CO)   // 12,845,056

// scratch (device globals; no allocation allowed)
__device__ float g_part[CHUNKS * 9 * BB * CC];   // 8.26 MB partial sums
__device__ float g_w2[9 * CC * NROUTES];          // conv_w @ fc_w / 784
__device__ float g_const[NROUTES];                // conv_b @ fc_w + fc_b
__device__ int   g_route[BB];

// ---------------------------------------------------------------------------
// w2 slice: W2[k][ci][r] = (1/784) * sum_co convw[k][ci][co] * fcw[co][r]
// ---------------------------------------------------------------------------
__device__ __forceinline__ void w2_work(int k,
                                        const float* __restrict__ convw,
                                        const float* __restrict__ convb,
                                        const float* __restrict__ fcw,
                                        const float* __restrict__ fcb,
                                        float* fsm) {
    const int t = threadIdx.x;
    if (t < CO * NROUTES) fsm[t] = fcw[t];
    __syncthreads();

    if (k < 9) {
        const int ci = t;
        const float* wrow = convw + ((size_t)k * CC + ci) * CO;
        float acc[NROUTES] = {0.f, 0.f, 0.f, 0.f};
        #pragma unroll 8
        for (int co = 0; co < CO; co++) {
            const float w = wrow[co];
            #pragma unroll
            for (int r = 0; r < NROUTES; r++)
                acc[r] += w * fsm[co * NROUTES + r];
        }
        #pragma unroll
        for (int r = 0; r < NROUTES; r++)
            g_w2[(k * CC + ci) * NROUTES + r] = acc[r] * (1.0f / 784.0f);
    } else if (t < NROUTES) {
        float c = fcb[t];
        for (int co = 0; co < CO; co++)
            c += convb[co] * fsm[co * NROUTES + t];
        g_const[t] = c;
    }
}

// ---------------------------------------------------------------------------
// Kernel 1: parity sums (+ merged w2 blocks at blockIdx.y == CHUNKS).
// grid (64, 15), 256 threads. Each 64-thread group handles one row
// (float4 = 4 ch/thread). Loads explicitly batched 8-deep (4 even + 4 odd
// float4) to raise MLP; launch_bounds gives ptxas 64 regs to hold them.
// ---------------------------------------------------------------------------
__global__ void __launch_bounds__(256, 4)
reduce_kernel(const float4* __restrict__ in,
              const float* __restrict__ convw,
              const float* __restrict__ convb,
              const float* __restrict__ fcw,
              const float* __restrict__ fcb) {
    __shared__ float sm[4 * 3 * CC];

    const int chunk = blockIdx.y;
    if (chunk == CHUNKS) {                 // w2 duty blocks
        if (blockIdx.x < 10)
            w2_work(blockIdx.x, convw, convb, fcw, fcb, sm);
        return;
    }

    const int b     = blockIdx.x;
    const int t     = threadIdx.x;
    const int row_i = t >> 6;        // 0..3
    const int cq    = t & 63;        // channel quad
    const int r     = chunk * 4 + row_i;

    const float4* row = in + ((size_t)(b * HH + r) * WW) * (CC / 4) + cq;

    float4 se = make_float4(0.f, 0.f, 0.f, 0.f);
    float4 so = make_float4(0.f, 0.f, 0.f, 0.f);
    const float4 v0 = __ldcs(&row[0]);

    // 7 groups x (4 even + 4 odd) float4 loads, front-batched inside group
    #pragma unroll
    for (int g = 0; g < 7; g++) {
        float4 e[4], o[4];
        #pragma unroll
        for (int i = 0; i < 4; i++) {
            const int p = g * 4 + i;
            e[i] = __ldcs(&row[(size_t)(2 * p)     * (CC / 4)]);
            o[i] = __ldcs(&row[(size_t)(2 * p + 1) * (CC / 4)]);
        }
        #pragma unroll
        for (int i = 0; i < 4; i++) {
            se.x += e[i].x; se.y += e[i].y; se.z += e[i].z; se.w += e[i].w;
            so.x += o[i].x; so.y += o[i].y; so.z += o[i].z; so.w += o[i].w;
        }
    }

    float4* smv = (float4*)sm;
    smv[(row_i * 3 + 0) * 64 + cq] = se;
    smv[(row_i * 3 + 1) * 64 + cq] = so;
    smv[(row_i * 3 + 2) * 64 + cq] = v0;
    __syncthreads();

    const int ch = t;
    #define SM(row, slot) sm[((row) * 3 + (slot)) * CC + ch]
    const float se0 = SM(0,0), se1 = SM(1,0), se2 = SM(2,0), se3 = SM(3,0);
    const float so0 = SM(0,1), so1 = SM(1,1), so2 = SM(2,1), so3 = SM(3,1);
    const float v00 = SM(0,2), v01 = SM(1,2), v02 = SM(2,2), v03 = SM(3,2);
    #undef SM

    const float zf = (chunk == 0) ? 1.f : 0.f;
    float outv[9];
    outv[0] = se0 + se2;        // t00 (even row, even col)
    outv[1] = so0 + so2;        // t01
    outv[2] = se1 + se3;        // t10
    outv[3] = so1 + so3;        // t11
    outv[4] = zf * se0;         // r0e
    outv[5] = zf * so0;         // r0o
    outv[6] = v00 + v02;        // c0e
    outv[7] = v01 + v03;        // c0o
    outv[8] = zf * v00;         // crn

    #pragma unroll
    for (int s = 0; s < 9; s++)
        g_part[(((size_t)chunk * 9 + s) * BB + b) * CC + ch] = outv[s];
}

// ---------------------------------------------------------------------------
// Kernel 2: per-batch routing. 64 blocks x 256 threads (thread = ci).
// ---------------------------------------------------------------------------
__global__ void route_kernel(const float* __restrict__ gamma,
                             const float* __restrict__ beta,
                             const float* __restrict__ mmean,
                             const float* __restrict__ mvar,
                             float* __restrict__ dout) {
    const int b = blockIdx.x;
    const int t = threadIdx.x;   // ci

    float s[9];
    #pragma unroll
    for (int k = 0; k < 9; k++) s[k] = 0.f;
    for (int chunk = 0; chunk < CHUNKS; chunk++) {
        #pragma unroll
        for (int k = 0; k < 9; k++)
            s[k] += __ldcs(&g_part[(((size_t)chunk * 9 + k) * BB + b) * CC + t]);
    }
    const float a  = gamma[t] * rsqrtf(mvar[t] + 1e-3f);
    const float bc = beta[t] - mmean[t] * a;

    const float T00 = s[0], T01 = s[1], T10 = s[2], T11 = s[3];
    const float R0E = s[4], R0O = s[5], C0E = s[6], C0O = s[7], CRN = s[8];
    const float S[9] = { T00, T01, T00 - C0E,
                         T10, T11, T10 - C0O,
                         T00 - R0E, T01 - R0O, T00 - C0E - R0E + CRN };
    const float cnt[9] = { 784.f, 784.f, 756.f, 784.f, 784.f, 756.f,
                           756.f, 756.f, 729.f };

    float4 acc = make_float4(0.f, 0.f, 0.f, 0.f);
    #pragma unroll
    for (int k = 0; k < 9; k++) {
        const float sbn = a * S[k] + bc * cnt[k];
        const float4 w = *(const float4*)&g_w2[(k * CC + t) * NROUTES];
        acc.x += sbn * w.x; acc.y += sbn * w.y;
        acc.z += sbn * w.z; acc.w += sbn * w.w;
    }

    __shared__ float4 red[256];
    red[t] = acc;
    __syncthreads();
    for (int off = 128; off >= 32; off >>= 1) {
        if (t < off) {
            float4 o = red[t + off];
            red[t].x += o.x; red[t].y += o.y; red[t].z += o.z; red[t].w += o.w;
        }
        __syncthreads();
    }
    if (t < 32) {
        float4 v = red[t];
        #pragma unroll
        for (int off = 16; off >= 1; off >>= 1) {
            v.x += __shfl_down_sync(0xffffffffu, v.x, off);
            v.y += __shfl_down_sync(0xffffffffu, v.y, off);
            v.z += __shfl_down_sync(0xffffffffu, v.z, off);
            v.w += __shfl_down_sync(0xffffffffu, v.w, off);
        }
        if (t == 0) {
            float rv[NROUTES] = { v.x + g_const[0], v.y + g_const[1],
                                  v.z + g_const[2], v.w + g_const[3] };
            int best = 0; float bv = rv[0];
            #pragma unroll
            for (int r = 1; r < NROUTES; r++)
                if (rv[r] > bv) { bv = rv[r]; best = r; }
            g_route[b] = best;
            #pragma unroll
            for (int r = 0; r < NROUTES; r++)
                dout[(size_t)X_ELEMS + b * NROUTES + r] = rv[r];
        }
    }
}

// ---------------------------------------------------------------------------
// Kernel 3: gather. grid (49, 64): y = batch (no divide), 4 float4 per
// thread, front-batched loads (MLP=4), coalesced 256B read / contiguous write.
// ---------------------------------------------------------------------------
__global__ void gather_kernel(const float4* __restrict__ in,
                              float4* __restrict__ out) {
    const int b = blockIdx.y;
    const int rt16 = g_route[b] * 16;
    const size_t bbase = (size_t)b * (HH * WW) * 16;   // float4 units of x

    const int f0 = blockIdx.x * 1024 + threadIdx.x;
    float4 v[4];
    #pragma unroll
    for (int i = 0; i < 4; i++) {
        const int f = f0 + i * 256;
        const int p = f >> 4;
        const int j = f & 15;
        v[i] = __ldcs(&in[bbase * 4 + (size_t)p * 64 + rt16 + j]);
    }
    #pragma unroll
    for (int i = 0; i < 4; i++)
        out[bbase + f0 + i * 256] = v[i];
}

// ---------------------------------------------------------------------------
extern "C" void kernel_launch(void* const* d_in, const int* in_sizes, int n_in,
                              void* d_out, int out_size) {
    const float* inputs = (const float*)d_in[0];
    const float* gamma  = (const float*)d_in[1];
    const float* beta   = (const float*)d_in[2];
    const float* mmean  = (const float*)d_in[3];
    const float* mvar   = (const float*)d_in[4];
    const float* convw  = (const float*)d_in[5];
    const float* convb  = (const float*)d_in[6];
    const float* fcw    = (const float*)d_in[7];
    const float* fcb    = (const float*)d_in[8];
    float* out = (float*)d_out;

    reduce_kernel<<<dim3(BB, CHUNKS + 1), 256>>>((const float4*)inputs,
                                                 convw, convb, fcw, fcb);
    route_kernel<<<BB, 256>>>(gamma, beta, mmean, mvar, out);
    gather_kernel<<<dim3(49, BB), 256>>>((const float4*)inputs, (float4*)out);
}

// round 10
// speedup vs baseline: 1.0642x; 1.0642x over previous
#include <cuda_runtime.h>

#define BB 64
#define HH 56
#define WW 56
#define CC 256
#define CO 64
#define NROUTES 4
#define CHUNKS 14
#define X_ELEMS (BB*HH*WW*CO)   // 12,845,056

// scratch (device globals; no allocation allowed)
__device__ float g_part[CHUNKS * 9 * BB * CC];   // 8.26 MB partial sums
__device__ float g_w2[9 * CC * NROUTES];          // conv_w @ fc_w / 784
__device__ float g_const[NROUTES];                // conv_b @ fc_w + fc_b
__device__ int   g_route[BB];

// ---------------------------------------------------------------------------
// w2 slice: W2[k][ci][r] = (1/784) * sum_co convw[k][ci][co] * fcw[co][r]
// ---------------------------------------------------------------------------
__device__ __forceinline__ void w2_work(int k,
                                        const float* __restrict__ convw,
                                        const float* __restrict__ convb,
                                        const float* __restrict__ fcw,
                                        const float* __restrict__ fcb,
                                        float* fsm) {
    const int t = threadIdx.x;
    if (t < CO * NROUTES) fsm[t] = fcw[t];
    __syncthreads();

    if (k < 9) {
        const int ci = t;
        const float* wrow = convw + ((size_t)k * CC + ci) * CO;
        float acc[NROUTES] = {0.f, 0.f, 0.f, 0.f};
        #pragma unroll 8
        for (int co = 0; co < CO; co++) {
            const float w = wrow[co];
            #pragma unroll
            for (int r = 0; r < NROUTES; r++)
                acc[r] += w * fsm[co * NROUTES + r];
        }
        #pragma unroll
        for (int r = 0; r < NROUTES; r++)
            g_w2[(k * CC + ci) * NROUTES + r] = acc[r] * (1.0f / 784.0f);
    } else if (t < NROUTES) {
        float c = fcb[t];
        for (int co = 0; co < CO; co++)
            c += convb[co] * fsm[co * NROUTES + t];
        g_const[t] = c;
    }
}

// ---------------------------------------------------------------------------
// Kernel 1: parity sums (+ merged w2 blocks at blockIdx.y == CHUNKS).
// grid (64, 15), 256 threads. Each 64-thread group handles one row
// (float4 = 4 ch/thread). 7 groups x (2 even + 2 odd) float4 loads;
// launch_bounds(256,6) targets ~40 regs -> 6 resident blocks + 4-deep
// per-thread load batching. v0 comes from the first even load (no dup).
// ---------------------------------------------------------------------------
__global__ void __launch_bounds__(256, 6)
reduce_kernel(const float4* __restrict__ in,
              const float* __restrict__ convw,
              const float* __restrict__ convb,
              const float* __restrict__ fcw,
              const float* __restrict__ fcb) {
    __shared__ float sm[4 * 3 * CC];

    const int chunk = blockIdx.y;
    if (chunk == CHUNKS) {                 // w2 duty blocks
        if (blockIdx.x < 10)
            w2_work(blockIdx.x, convw, convb, fcw, fcb, sm);
        return;
    }

    const int b     = blockIdx.x;
    const int t     = threadIdx.x;
    const int row_i = t >> 6;        // 0..3
    const int cq    = t & 63;        // channel quad
    const int r     = chunk * 4 + row_i;

    const float4* row = in + ((size_t)(b * HH + r) * WW) * (CC / 4) + cq;

    float4 se = make_float4(0.f, 0.f, 0.f, 0.f);
    float4 so = make_float4(0.f, 0.f, 0.f, 0.f);
    float4 v0;

    #pragma unroll
    for (int g = 0; g < 7; g++) {
        float4 e0 = __ldcs(&row[(size_t)(8 * g)     * (CC / 4)]);
        float4 o0 = __ldcs(&row[(size_t)(8 * g + 1) * (CC / 4)]);
        float4 e1 = __ldcs(&row[(size_t)(8 * g + 2) * (CC / 4)]);
        float4 o1 = __ldcs(&row[(size_t)(8 * g + 3) * (CC / 4)]);
        if (g == 0) v0 = e0;
        se.x += e0.x + e1.x; se.y += e0.y + e1.y;
        se.z += e0.z + e1.z; se.w += e0.w + e1.w;
        so.x += o0.x + o1.x; so.y += o0.y + o1.y;
        so.z += o0.z + o1.z; so.w += o0.w + o1.w;

        float4 e2 = __ldcs(&row[(size_t)(8 * g + 4) * (CC / 4)]);
        float4 o2 = __ldcs(&row[(size_t)(8 * g + 5) * (CC / 4)]);
        float4 e3 = __ldcs(&row[(size_t)(8 * g + 6) * (CC / 4)]);
        float4 o3 = __ldcs(&row[(size_t)(8 * g + 7) * (CC / 4)]);
        se.x += e2.x + e3.x; se.y += e2.y + e3.y;
        se.z += e2.z + e3.z; se.w += e2.w + e3.w;
        so.x += o2.x + o3.x; so.y += o2.y + o3.y;
        so.z += o2.z + o3.z; so.w += o2.w + o3.w;
    }

    float4* smv = (float4*)sm;
    smv[(row_i * 3 + 0) * 64 + cq] = se;
    smv[(row_i * 3 + 1) * 64 + cq] = so;
    smv[(row_i * 3 + 2) * 64 + cq] = v0;
    __syncthreads();

    const int ch = t;
    #define SM(row, slot) sm[((row) * 3 + (slot)) * CC + ch]
    const float se0 = SM(0,0), se1 = SM(1,0), se2 = SM(2,0), se3 = SM(3,0);
    const float so0 = SM(0,1), so1 = SM(1,1), so2 = SM(2,1), so3 = SM(3,1);
    const float v00 = SM(0,2), v01 = SM(1,2), v02 = SM(2,2), v03 = SM(3,2);
    #undef SM

    const float zf = (chunk == 0) ? 1.f : 0.f;
    float outv[9];
    outv[0] = se0 + se2;        // t00 (even row, even col)
    outv[1] = so0 + so2;        // t01
    outv[2] = se1 + se3;        // t10
    outv[3] = so1 + so3;        // t11
    outv[4] = zf * se0;         // r0e
    outv[5] = zf * so0;         // r0o
    outv[6] = v00 + v02;        // c0e
    outv[7] = v01 + v03;        // c0o
    outv[8] = zf * v00;         // crn

    #pragma unroll
    for (int s = 0; s < 9; s++)
        g_part[(((size_t)chunk * 9 + s) * BB + b) * CC + ch] = outv[s];
}

// ---------------------------------------------------------------------------
// Kernel 2: per-batch routing. 64 blocks x 256 threads (thread = ci).
// ---------------------------------------------------------------------------
__global__ void route_kernel(const float* __restrict__ gamma,
                             const float* __restrict__ beta,
                             const float* __restrict__ mmean,
                             const float* __restrict__ mvar,
                             float* __restrict__ dout) {
    const int b = blockIdx.x;
    const int t = threadIdx.x;   // ci

    float s[9];
    #pragma unroll
    for (int k = 0; k < 9; k++) s[k] = 0.f;
    for (int chunk = 0; chunk < CHUNKS; chunk++) {
        #pragma unroll
        for (int k = 0; k < 9; k++)
            s[k] += __ldcs(&g_part[(((size_t)chunk * 9 + k) * BB + b) * CC + t]);
    }
    const float a  = gamma[t] * rsqrtf(mvar[t] + 1e-3f);
    const float bc = beta[t] - mmean[t] * a;

    const float T00 = s[0], T01 = s[1], T10 = s[2], T11 = s[3];
    const float R0E = s[4], R0O = s[5], C0E = s[6], C0O = s[7], CRN = s[8];
    const float S[9] = { T00, T01, T00 - C0E,
                         T10, T11, T10 - C0O,
                         T00 - R0E, T01 - R0O, T00 - C0E - R0E + CRN };
    const float cnt[9] = { 784.f, 784.f, 756.f, 784.f, 784.f, 756.f,
                           756.f, 756.f, 729.f };

    float4 acc = make_float4(0.f, 0.f, 0.f, 0.f);
    #pragma unroll
    for (int k = 0; k < 9; k++) {
        const float sbn = a * S[k] + bc * cnt[k];
        const float4 w = *(const float4*)&g_w2[(k * CC + t) * NROUTES];
        acc.x += sbn * w.x; acc.y += sbn * w.y;
        acc.z += sbn * w.z; acc.w += sbn * w.w;
    }

    __shared__ float4 red[256];
    red[t] = acc;
    __syncthreads();
    for (int off = 128; off >= 32; off >>= 1) {
        if (t < off) {
            float4 o = red[t + off];
            red[t].x += o.x; red[t].y += o.y; red[t].z += o.z; red[t].w += o.w;
        }
        __syncthreads();
    }
    if (t < 32) {
        float4 v = red[t];
        #pragma unroll
        for (int off = 16; off >= 1; off >>= 1) {
            v.x += __shfl_down_sync(0xffffffffu, v.x, off);
            v.y += __shfl_down_sync(0xffffffffu, v.y, off);
            v.z += __shfl_down_sync(0xffffffffu, v.z, off);
            v.w += __shfl_down_sync(0xffffffffu, v.w, off);
        }
        if (t == 0) {
            float rv[NROUTES] = { v.x + g_const[0], v.y + g_const[1],
                                  v.z + g_const[2], v.w + g_const[3] };
            int best = 0; float bv = rv[0];
            #pragma unroll
            for (int r = 1; r < NROUTES; r++)
                if (rv[r] > bv) { bv = rv[r]; best = r; }
            g_route[b] = best;
            #pragma unroll
            for (int r = 0; r < NROUTES; r++)
                dout[(size_t)X_ELEMS + b * NROUTES + r] = rv[r];
        }
    }
}

// ---------------------------------------------------------------------------
// Kernel 3: gather. grid (49, 64): y = batch (no divide), 4 float4 per
// thread, front-batched loads (MLP=4), coalesced 256B read / contiguous write.
// ---------------------------------------------------------------------------
__global__ void gather_kernel(const float4* __restrict__ in,
                              float4* __restrict__ out) {
    const int b = blockIdx.y;
    const int rt16 = g_route[b] * 16;
    const size_t bbase = (size_t)b * (HH * WW) * 16;   // float4 units of x

    const int f0 = blockIdx.x * 1024 + threadIdx.x;
    float4 v[4];
    #pragma unroll
    for (int i = 0; i < 4; i++) {
        const int f = f0 + i * 256;
        const int p = f >> 4;
        const int j = f & 15;
        v[i] = __ldcs(&in[bbase * 4 + (size_t)p * 64 + rt16 + j]);
    }
    #pragma unroll
    for (int i = 0; i < 4; i++)
        out[bbase + f0 + i * 256] = v[i];
}

// ---------------------------------------------------------------------------
extern "C" void kernel_launch(void* const* d_in, const int* in_sizes, int n_in,
                              void* d_out, int out_size) {
    const float* inputs = (const float*)d_in[0];
    const float* gamma  = (const float*)d_in[1];
    const float* beta   = (const float*)d_in[2];
    const float* mmean  = (const float*)d_in[3];
    const float* mvar   = (const float*)d_in[4];
    const float* convw  = (const float*)d_in[5];
    const float* convb  = (const float*)d_in[6];
    const float* fcw    = (const float*)d_in[7];
    const float* fcb    = (const float*)d_in[8];
    float* out = (float*)d_out;

    reduce_kernel<<<dim3(BB, CHUNKS + 1), 256>>>((const float4*)inputs,
                                                 convw, convb, fcw, fcb);
    route_kernel<<<BB, 256>>>(gamma, beta, mmean, mvar, out);
    gather_kernel<<<dim3(49, BB), 256>>>((const float4*)inputs, (float4*)out);
}

// round 13
// speedup vs baseline: 1.0725x; 1.0078x over previous
#include <cuda_runtime.h>

#define BB 64
#define HH 56
#define WW 56
#define CC 256
#define CO 64
#define NROUTES 4
#define CHUNKS 7                 // 8 rows per chunk now
#define X_ELEMS (BB*HH*WW*CO)   // 12,845,056

// scratch (device globals; no allocation allowed)
__device__ float g_part[CHUNKS * 9 * BB * CC];   // 4.13 MB partial sums
__device__ float g_w2[9 * CC * NROUTES];          // conv_w @ fc_w / 784
__device__ float g_const[NROUTES];                // conv_b @ fc_w + fc_b
__device__ int   g_route[BB];

// ---------------------------------------------------------------------------
// Kernel 1: parity sums. grid (64, 8): y=0..6 worker chunks (8 rows each),
// y=7 duty blocks (x<10) computing W2 = conv_w @ fc_w / 784 and g_const.
// 512 threads: 8 independent 64-thread row groups (float4 = 4 ch/thread),
// smem transpose, epilogue split across thread halves. Single-wave:
// 448 workers vs 444 resident (3 blocks/SM, 75% occ).
// ---------------------------------------------------------------------------
__global__ void __launch_bounds__(512, 3)
reduce_kernel(const float4* __restrict__ in,
              const float* __restrict__ convw,
              const float* __restrict__ convb,
              const float* __restrict__ fcw,
              const float* __restrict__ fcb) {
    __shared__ float sm[8 * 3 * CC];     // 24 KB

    const int chunk = blockIdx.y;
    const int t     = threadIdx.x;

    if (chunk == CHUNKS) {               // ---- w2 duty blocks ----
        if (blockIdx.x >= 10) return;
        __shared__ float fsm[CO * NROUTES];
        if (t < CO * NROUTES) fsm[t] = fcw[t];
        __syncthreads();
        const int k = blockIdx.x;
        if (k < 9) {
            if (t < CC) {
                const int ci = t;
                const float* wrow = convw + ((size_t)k * CC + ci) * CO;
                float acc[NROUTES] = {0.f, 0.f, 0.f, 0.f};
                #pragma unroll 8
                for (int co = 0; co < CO; co++) {
                    const float w = wrow[co];
                    #pragma unroll
                    for (int r = 0; r < NROUTES; r++)
                        acc[r] += w * fsm[co * NROUTES + r];
                }
                #pragma unroll
                for (int r = 0; r < NROUTES; r++)
                    g_w2[(k * CC + ci) * NROUTES + r] = acc[r] * (1.0f / 784.0f);
            }
        } else if (t < NROUTES) {
            float c = fcb[t];
            for (int co = 0; co < CO; co++)
                c += convb[co] * fsm[co * NROUTES + t];
            g_const[t] = c;
        }
        return;
    }

    // ---- worker: 8 rows in parallel ----
    const int b     = blockIdx.x;
    const int row_i = t >> 6;        // 0..7
    const int cq    = t & 63;        // channel quad
    const int r     = chunk * 8 + row_i;

    const float4* row = in + ((size_t)(b * HH + r) * WW) * (CC / 4) + cq;

    float4 se = make_float4(0.f, 0.f, 0.f, 0.f);
    float4 so = make_float4(0.f, 0.f, 0.f, 0.f);
    float4 v0;

    #pragma unroll
    for (int g = 0; g < 7; g++) {
        float4 e0 = __ldcs(&row[(size_t)(8 * g)     * (CC / 4)]);
        float4 o0 = __ldcs(&row[(size_t)(8 * g + 1) * (CC / 4)]);
        float4 e1 = __ldcs(&row[(size_t)(8 * g + 2) * (CC / 4)]);
        float4 o1 = __ldcs(&row[(size_t)(8 * g + 3) * (CC / 4)]);
        if (g == 0) v0 = e0;
        se.x += e0.x + e1.x; se.y += e0.y + e1.y;
        se.z += e0.z + e1.z; se.w += e0.w + e1.w;
        so.x += o0.x + o1.x; so.y += o0.y + o1.y;
        so.z += o0.z + o1.z; so.w += o0.w + o1.w;

        float4 e2 = __ldcs(&row[(size_t)(8 * g + 4) * (CC / 4)]);
        float4 o2 = __ldcs(&row[(size_t)(8 * g + 5) * (CC / 4)]);
        float4 e3 = __ldcs(&row[(size_t)(8 * g + 6) * (CC / 4)]);
        float4 o3 = __ldcs(&row[(size_t)(8 * g + 7) * (CC / 4)]);
        se.x += e2.x + e3.x; se.y += e2.y + e3.y;
        se.z += e2.z + e3.z; se.w += e2.w + e3.w;
        so.x += o2.x + o3.x; so.y += o2.y + o3.y;
        so.z += o2.z + o3.z; so.w += o2.w + o3.w;
    }

    float4* smv = (float4*)sm;
    smv[(row_i * 3 + 0) * 64 + cq] = se;
    smv[(row_i * 3 + 1) * 64 + cq] = so;
    smv[(row_i * 3 + 2) * 64 + cq] = v0;
    __syncthreads();

    const int ch   = t & 255;
    const int half = t >> 8;
    const float zf = (chunk == 0) ? 1.f : 0.f;
    #define SMv(row, slot) sm[((row) * 3 + (slot)) * CC + ch]
    #define GP(s) g_part[(((size_t)chunk * 9 + (s)) * BB + b) * CC + ch]

    if (half == 0) {
        // even rows: t00, t01, r0e, r0o, c0e
        const float se0 = SMv(0,0), se2 = SMv(2,0), se4 = SMv(4,0), se6 = SMv(6,0);
        const float so0 = SMv(0,1), so2 = SMv(2,1), so4 = SMv(4,1), so6 = SMv(6,1);
        const float v00 = SMv(0,2), v02 = SMv(2,2), v04 = SMv(4,2), v06 = SMv(6,2);
        GP(0) = se0 + se2 + se4 + se6;        // t00
        GP(1) = so0 + so2 + so4 + so6;        // t01
        GP(4) = zf * se0;                     // r0e
        GP(5) = zf * so0;                     // r0o
        GP(6) = v00 + v02 + v04 + v06;        // c0e
    } else {
        // odd rows: t10, t11, c0o, crn
        const float se1 = SMv(1,0), se3 = SMv(3,0), se5 = SMv(5,0), se7 = SMv(7,0);
        const float so1 = SMv(1,1), so3 = SMv(3,1), so5 = SMv(5,1), so7 = SMv(7,1);
        const float v01 = SMv(1,2), v03 = SMv(3,2), v05 = SMv(5,2), v07 = SMv(7,2);
        GP(2) = se1 + se3 + se5 + se7;        // t10
        GP(3) = so1 + so3 + so5 + so7;        // t11
        GP(7) = v01 + v03 + v05 + v07;        // c0o
        GP(8) = zf * SMv(0,2);                // crn
    }
    #undef SMv
    #undef GP
}

// ---------------------------------------------------------------------------
// Kernel 2: per-batch routing. 64 blocks x 256 threads (thread = ci).
// ---------------------------------------------------------------------------
__global__ void route_kernel(const float* __restrict__ gamma,
                             const float* __restrict__ beta,
                             const float* __restrict__ mmean,
                             const float* __restrict__ mvar,
                             float* __restrict__ dout) {
    const int b = blockIdx.x;
    const int t = threadIdx.x;   // ci

    float s[9];
    #pragma unroll
    for (int k = 0; k < 9; k++) s[k] = 0.f;
    #pragma unroll
    for (int chunk = 0; chunk < CHUNKS; chunk++) {
        #pragma unroll
        for (int k = 0; k < 9; k++)
            s[k] += __ldcs(&g_part[(((size_t)chunk * 9 + k) * BB + b) * CC + t]);
    }
    const float a  = gamma[t] * rsqrtf(mvar[t] + 1e-3f);
    const float bc = beta[t] - mmean[t] * a;

    const float T00 = s[0], T01 = s[1], T10 = s[2], T11 = s[3];
    const float R0E = s[4], R0O = s[5], C0E = s[6], C0O = s[7], CRN = s[8];
    const float S[9] = { T00, T01, T00 - C0E,
                         T10, T11, T10 - C0O,
                         T00 - R0E, T01 - R0O, T00 - C0E - R0E + CRN };
    const float cnt[9] = { 784.f, 784.f, 756.f, 784.f, 784.f, 756.f,
                           756.f, 756.f, 729.f };

    float4 acc = make_float4(0.f, 0.f, 0.f, 0.f);
    #pragma unroll
    for (int k = 0; k < 9; k++) {
        const float sbn = a * S[k] + bc * cnt[k];
        const float4 w = *(const float4*)&g_w2[(k * CC + t) * NROUTES];
        acc.x += sbn * w.x; acc.y += sbn * w.y;
        acc.z += sbn * w.z; acc.w += sbn * w.w;
    }

    __shared__ float4 red[256];
    red[t] = acc;
    __syncthreads();
    for (int off = 128; off >= 32; off >>= 1) {
        if (t < off) {
            float4 o = red[t + off];
            red[t].x += o.x; red[t].y += o.y; red[t].z += o.z; red[t].w += o.w;
        }
        __syncthreads();
    }
    if (t < 32) {
        float4 v = red[t];
        #pragma unroll
        for (int off = 16; off >= 1; off >>= 1) {
            v.x += __shfl_down_sync(0xffffffffu, v.x, off);
            v.y += __shfl_down_sync(0xffffffffu, v.y, off);
            v.z += __shfl_down_sync(0xffffffffu, v.z, off);
            v.w += __shfl_down_sync(0xffffffffu, v.w, off);
        }
        if (t == 0) {
            float rv[NROUTES] = { v.x + g_const[0], v.y + g_const[1],
                                  v.z + g_const[2], v.w + g_const[3] };
            int best = 0; float bv = rv[0];
            #pragma unroll
            for (int r = 1; r < NROUTES; r++)
                if (rv[r] > bv) { bv = rv[r]; best = r; }
            g_route[b] = best;
            #pragma unroll
            for (int r = 0; r < NROUTES; r++)
                dout[(size_t)X_ELEMS + b * NROUTES + r] = rv[r];
        }
    }
}

// ---------------------------------------------------------------------------
// Kernel 3: gather. grid (49, 64): y = batch (no divide), 4 float4 per
// thread, front-batched loads (MLP=4), coalesced 256B read / contiguous write.
// ---------------------------------------------------------------------------
__global__ void gather_kernel(const float4* __restrict__ in,
                              float4* __restrict__ out) {
    const int b = blockIdx.y;
    const int rt16 = g_route[b] * 16;
    const size_t bbase = (size_t)b * (HH * WW) * 16;   // float4 units of x

    const int f0 = blockIdx.x * 1024 + threadIdx.x;
    float4 v[4];
    #pragma unroll
    for (int i = 0; i < 4; i++) {
        const int f = f0 + i * 256;
        const int p = f >> 4;
        const int j = f & 15;
        v[i] = __ldcs(&in[bbase * 4 + (size_t)p * 64 + rt16 + j]);
    }
    #pragma unroll
    for (int i = 0; i < 4; i++)
        out[bbase + f0 + i * 256] = v[i];
}

// ---------------------------------------------------------------------------
extern "C" void kernel_launch(void* const* d_in, const int* in_sizes, int n_in,
                              void* d_out, int out_size) {
    const float* inputs = (const float*)d_in[0];
    const float* gamma  = (const float*)d_in[1];
    const float* beta   = (const float*)d_in[2];
    const float* mmean  = (const float*)d_in[3];
    const float* mvar   = (const float*)d_in[4];
    const float* convw  = (const float*)d_in[5];
    const float* convb  = (const float*)d_in[6];
    const float* fcw    = (const float*)d_in[7];
    const float* fcb    = (const float*)d_in[8];
    float* out = (float*)d_out;

    reduce_kernel<<<dim3(BB, CHUNKS + 1), 512>>>((const float4*)inputs,
                                                 convw, convb, fcw, fcb);
    route_kernel<<<BB, 256>>>(gamma, beta, mmean, mvar, out);
    gather_kernel<<<dim3(49, BB), 256>>>((const float4*)inputs, (float4*)out);
}